// round 15
// baseline (speedup 1.0000x reference)
#include <cuda_runtime.h>
#include <cuda_bf16.h>
#include <math.h>
#include <stdint.h>

constexpr int Dm = 1024;   // dim == seq len L
constexpr int Ns = 16;     // SSM state size
constexpr int KC = 3 * Dm; // conv GEMM K = 3072

// ---------------- scratch (static device globals: allocation-free) ----------
__device__ int8_t g_xq1[2 * Dm * Dm], g_xq2[2 * Dm * Dm];
__device__ int8_t g_Wpq1[Dm * Dm],  g_Wpq2[Dm * Dm];
__device__ int8_t g_cwq1[Dm * KC],  g_cwq2[Dm * KC];
__device__ float  g_WdTf[Dm * Dm];
__device__ int8_t g_WdTq1[Dm * Dm], g_WdTq2[Dm * Dm];
__device__ int8_t g_cBq1[Dm * KC],  g_cBq2[Dm * KC];
__device__ int8_t g_xcq1[Dm * Dm],  g_xcq2[Dm * Dm];
__device__ int8_t g_yq1[Dm * Dm],   g_yq2[Dm * Dm];
__device__ int8_t g_xgq1[Dm * Dm],  g_xgq2[Dm * Dm];
__device__ int8_t g_tq1[Dm * Dm],   g_tq2[Dm * Dm];
__device__ float g_p0[Dm * Dm];
__device__ float g_xgf[Dm * Dm];
__device__ float g_xc[Dm * Dm];
__device__ float g_delta[Dm * Dm];
__device__ float g_yf[Dm * Dm];
__device__ float g_tf[Dm * Dm];
__device__ float g_Bm[Dm * Ns], g_Cm[Dm * Ns];
__device__ float g_scx[2 * Dm], g_scWp[Dm], g_sccw[Dm], g_scWdT[Dm];
__device__ float g_scCB[Dm], g_scxc[Dm], g_scy[Dm], g_scxg[Dm], g_sct[Dm];
__device__ float g_colmax[Dm];

__device__ __forceinline__ float sigmoidf_(float x) {
    return 1.0f / (1.0f + expf(-x));
}

__device__ __forceinline__ uint32_t smem_u32(const void* p) {
    uint32_t a;
    asm("{ .reg .u64 t; cvta.to.shared.u64 t, %1; cvt.u32.u64 %0, t; }" : "=r"(a) : "l"(p));
    return a;
}

#define SWZ(x) ((x) ^ (((x) >> 3) & 0x70))

__device__ __forceinline__ void cpa16(uint32_t dst, const void* src) {
    asm volatile("cp.async.cg.shared.global [%0], [%1], 16;" :: "r"(dst), "l"(src));
}

#define MMA_S8(c, a, b0, b1)                                                     \
    asm volatile(                                                                \
        "mma.sync.aligned.m16n8k32.row.col.s32.s8.s8.s32 "                       \
        "{%0,%1,%2,%3},{%4,%5,%6,%7},{%8,%9},{%0,%1,%2,%3};"                     \
        : "+r"(c[0]), "+r"(c[1]), "+r"(c[2]), "+r"(c[3])                         \
        : "r"(a[0]), "r"(a[1]), "r"(a[2]), "r"(a[3]), "r"(b0), "r"(b1))

#define LDSM_X4(r0, r1, r2, r3, addr)                                            \
    asm volatile("ldmatrix.sync.aligned.m8n8.x4.shared.b16 {%0,%1,%2,%3}, [%4];" \
        : "=r"(r0), "=r"(r1), "=r"(r2), "=r"(r3) : "r"(addr))

// ---------------- block max (256 threads) ------------------------------------
__device__ __forceinline__ float block_max(float m, float* red) {
    const int tid = threadIdx.x;
#pragma unroll
    for (int off = 16; off; off >>= 1)
        m = fmaxf(m, __shfl_xor_sync(0xffffffffu, m, off));
    if ((tid & 31) == 0) red[tid >> 5] = m;
    __syncthreads();
    if (tid < 32) {
        float t = (tid < 8) ? red[tid] : 0.0f;
#pragma unroll
        for (int off = 4; off; off >>= 1)
            t = fmaxf(t, __shfl_xor_sync(0xffffffffu, t, off));
        if (tid == 0) red[0] = t;
    }
    __syncthreads();
    return red[0];
}

// ---------------- two-level int8 row quantization -----------------------------
// x ~ s*(q1 + q2/256), s = rowmax/127
template <int V>   // float4 chunks per thread (V=1 -> row 1024, V=3 -> 3072)
__device__ __forceinline__ void quant_row_dev(const float* __restrict__ rp,
                                              int8_t* __restrict__ q1,
                                              int8_t* __restrict__ q2,
                                              float* __restrict__ scOut,
                                              float* red) {
    const int tid = threadIdx.x;
    float4 v[V];
    float m = 0.0f;
#pragma unroll
    for (int i = 0; i < V; i++) {
        v[i] = ((const float4*)rp)[tid + i * 256];
        m = fmaxf(m, fmaxf(fmaxf(fabsf(v[i].x), fabsf(v[i].y)),
                           fmaxf(fabsf(v[i].z), fabsf(v[i].w))));
    }
    float mx = fmaxf(block_max(m, red), 1e-20f);
    float inv = 127.0f / mx;
    if (tid == 0) *scOut = mx * (1.0f / 127.0f);
#pragma unroll
    for (int i = 0; i < V; i++) {
        float f[4] = {v[i].x * inv, v[i].y * inv, v[i].z * inv, v[i].w * inv};
        char c1[4], c2[4];
#pragma unroll
        for (int j = 0; j < 4; j++) {
            float a = rintf(f[j]);
            float b = fminf(fmaxf(rintf((f[j] - a) * 256.0f), -127.0f), 127.0f);
            c1[j] = (char)(int)a;
            c2[j] = (char)(int)b;
        }
        ((int*)q1)[tid + i * 256] = *(int*)c1;
        ((int*)q2)[tid + i * 256] = *(int*)c2;
    }
}

__global__ void __launch_bounds__(256) quant_g1024(const float* __restrict__ in,
                                                   int8_t* __restrict__ q1,
                                                   int8_t* __restrict__ q2,
                                                   float* __restrict__ sc) {
    __shared__ float red[8];
    const size_t off = (size_t)blockIdx.x * Dm;
    quant_row_dev<1>(in + off, q1 + off, q2 + off, &sc[blockIdx.x], red);
}

// ---------------- fused prep: quantize x/Wp/cw + transpose Wd + init colmax ---
__global__ void __launch_bounds__(256) prep_fused(
    const float* __restrict__ x,  int8_t* __restrict__ xq1, int8_t* __restrict__ xq2, float* __restrict__ scx,
    const float* __restrict__ Wp, int8_t* __restrict__ Wpq1, int8_t* __restrict__ Wpq2, float* __restrict__ scWp,
    const float* __restrict__ cw, int8_t* __restrict__ cwq1, int8_t* __restrict__ cwq2, float* __restrict__ sccw,
    const float* __restrict__ Wd, float* __restrict__ WdTf, float* __restrict__ colmax)
{
    __shared__ float red[8];
    __shared__ float t[32][33];
    const int b = blockIdx.x;
    if (b < 2048) {
        const size_t off = (size_t)b * Dm;
        quant_row_dev<1>(x + off, xq1 + off, xq2 + off, &scx[b], red);
    } else if (b < 3072) {
        const size_t off = (size_t)(b - 2048) * Dm;
        quant_row_dev<1>(Wp + off, Wpq1 + off, Wpq2 + off, &scWp[b - 2048], red);
    } else if (b < 4096) {
        const size_t off = (size_t)(b - 3072) * KC;
        quant_row_dev<3>(cw + off, cwq1 + off, cwq2 + off, &sccw[b - 3072], red);
    } else if (b < 5120) {
        int bi = b - 4096;
        int x0 = (bi & 31) * 32, y0 = (bi >> 5) * 32;
        int tx = threadIdx.x & 31, ty0 = threadIdx.x >> 5;
        for (int j = ty0; j < 32; j += 8)
            t[j][tx] = Wd[(y0 + j) * Dm + x0 + tx];
        __syncthreads();
        for (int j = ty0; j < 32; j += 8)
            WdTf[(size_t)(x0 + j) * Dm + y0 + tx] = t[tx][j];
    } else {
        // init colmax
        *(float4*)&colmax[threadIdx.x * 4] = make_float4(0.f, 0.f, 0.f, 0.f);
    }
}

// ---------------- column max of |p0| ------------------------------------------
__global__ void __launch_bounds__(256) colmax_k(const float* __restrict__ P0,
                                                float* __restrict__ cm) {
    const int r0 = blockIdx.x * 32;
    const int c4 = threadIdx.x * 4;
    float4 acc = make_float4(0.f, 0.f, 0.f, 0.f);
    for (int r = 0; r < 32; r++) {
        float4 v = *(const float4*)(P0 + (size_t)(r0 + r) * Dm + c4);
        acc.x = fmaxf(acc.x, fabsf(v.x));
        acc.y = fmaxf(acc.y, fabsf(v.y));
        acc.z = fmaxf(acc.z, fabsf(v.z));
        acc.w = fmaxf(acc.w, fabsf(v.w));
    }
    atomicMax((int*)&cm[c4 + 0], __float_as_int(acc.x));
    atomicMax((int*)&cm[c4 + 1], __float_as_int(acc.y));
    atomicMax((int*)&cm[c4 + 2], __float_as_int(acc.z));
    atomicMax((int*)&cm[c4 + 3], __float_as_int(acc.w));
}

// ---------------- conv B build, quantized -------------------------------------
// B[d, i*3+kk] = p0[i, d-1+kk]; scale[d] from colmax window.
__global__ void __launch_bounds__(256) conv_b_q(const float* __restrict__ P0,
                                                const float* __restrict__ cm,
                                                int8_t* __restrict__ q1,
                                                int8_t* __restrict__ q2,
                                                float* __restrict__ scB) {
    __shared__ float Xs[32][35];
    int d0 = blockIdx.x * 32, i0 = blockIdx.y * 32;
    int tid = threadIdx.x;
    for (int idx = tid; idx < 32 * 34; idx += 256) {
        int r = idx / 34, c = idx % 34;
        int gd = d0 - 1 + c;
        Xs[r][c] = (gd >= 0 && gd < Dm) ? P0[(size_t)(i0 + r) * Dm + gd] : 0.0f;
    }
    __syncthreads();
    int i = tid & 31;
    for (int dl = tid >> 5; dl < 32; dl += 8) {
        int d = d0 + dl;
        float m0 = (d > 0) ? cm[d - 1] : 0.0f;
        float m1 = cm[d];
        float m2 = (d < Dm - 1) ? cm[d + 1] : 0.0f;
        float mx = fmaxf(fmaxf(m0, m1), fmaxf(m2, 1e-20f));
        float inv = 127.0f / mx;
        if (blockIdx.y == 0 && i == 0) scB[d] = mx * (1.0f / 127.0f);
        size_t base = (size_t)d * KC + (size_t)(i0 + i) * 3;
#pragma unroll
        for (int kk = 0; kk < 3; kk++) {
            float f = Xs[i][dl + kk] * inv;
            float a = rintf(f);
            float b = fminf(fmaxf(rintf((f - a) * 256.0f), -127.0f), 127.0f);
            q1[base + kk] = (char)(int)a;
            q2[base + kk] = (char)(int)b;
        }
    }
}

// ---------------- int8 3-term IMMA GEMM ---------------------------------------
// C[m,n] = sA[m]*sB[n]*(Σq1q1 + (Σq1q2 + Σq2q1)/256), fp32 output.
// EPI: 0 none, 1 +bias, 2 +bias+silu, 3 softplus. DUAL: rows>=1024 -> silu -> Cf2.
template <int EPI, bool BIASROW, bool DUAL>
__global__ void __launch_bounds__(256, 1)
gemm_i8(const int8_t* __restrict__ Aq1, const int8_t* __restrict__ Aq2,
        const int8_t* __restrict__ Bq1, const int8_t* __restrict__ Bq2,
        const float* __restrict__ sA, const float* __restrict__ sB,
        const float* __restrict__ bias,
        float* __restrict__ Cf, float* __restrict__ Cf2, int Nn, int K)
{
    constexpr int TM = 128, TN = 64, NT = 256;
    constexpr int OFF_A2 = TM * 128;
    constexpr int OFF_B1 = TM * 256;
    constexpr int BL = TN * 128;
    constexpr int STAGEB = (TM + TN) * 256;  // 48KB
    constexpr int NBUF = 4, DEPTH = 3;
    constexpr int NJ = 4, NG = 2;            // warp tile 32x32

    extern __shared__ __align__(1024) char dyns[];
    const int tid = threadIdx.x;
    const int lane = tid & 31, warp = tid >> 5;
    const int m0 = blockIdx.y * TM, n0 = blockIdx.x * TN;
    const uint32_t dbase = smem_u32(dyns);
    const int S = K >> 7;   // 128 int8 k per stage

    int acc0[2][NJ][4], acc1[2][NJ][4];
#pragma unroll
    for (int a = 0; a < 2; a++)
#pragma unroll
        for (int b = 0; b < NJ; b++)
#pragma unroll
            for (int c = 0; c < 4; c++) { acc0[a][b][c] = 0; acc1[a][b][c] = 0; }

    auto load_stage = [&](int s) {
        const uint32_t sb = dbase + (s % NBUF) * STAGEB;
        const int k0 = s << 7;
#pragma unroll
        for (int i = 0; i < 4; i++) {
            int q = tid + i * NT;
            int r = q >> 3, c = q & 7;
            uint32_t so = SWZ((uint32_t)(r * 128 + c * 16));
            size_t ga = (size_t)(m0 + r) * K + k0 + c * 16;
            cpa16(sb + so, Aq1 + ga);
            cpa16(sb + OFF_A2 + so, Aq2 + ga);
        }
#pragma unroll
        for (int i = 0; i < 2; i++) {
            int q = tid + i * NT;
            int r = q >> 3, c = q & 7;
            uint32_t so = SWZ((uint32_t)(r * 128 + c * 16));
            size_t gb = (size_t)(n0 + r) * K + k0 + c * 16;
            cpa16(sb + OFF_B1 + so, Bq1 + gb);
            cpa16(sb + OFF_B1 + BL + so, Bq2 + gb);
        }
        asm volatile("cp.async.commit_group;" ::: "memory");
    };

#pragma unroll
    for (int s = 0; s < DEPTH; s++) load_stage(s);

    const int wm = (warp & 3) * 32, wn = (warp >> 2) * 32;
    const uint32_t frow = (lane & 7) + ((lane >> 3) & 1) * 8;
    const uint32_t fxor = (frow & 7) << 4;
    const uint32_t fcol = (lane >> 4) << 4;

    for (int s = 0; s < S; s++) {
        asm volatile("cp.async.wait_group %0;" :: "n"(DEPTH - 1) : "memory");
        __syncthreads();
        if (s + DEPTH < S) load_stage(s + DEPTH);
        else asm volatile("cp.async.commit_group;" ::: "memory");

        const uint32_t sb = dbase + (s % NBUF) * STAGEB;
#pragma unroll
        for (int ks = 0; ks < 4; ks++) {
            const uint32_t kc = (uint32_t)(ks * 32 + fcol) ^ fxor;
            uint32_t a1[2][4], a2[2][4], b1[NG][4], b2[NG][4];
#pragma unroll
            for (int mi = 0; mi < 2; mi++) {
                uint32_t ra = sb + (wm + mi * 16 + frow) * 128 + kc;
                LDSM_X4(a1[mi][0], a1[mi][1], a1[mi][2], a1[mi][3], ra);
                LDSM_X4(a2[mi][0], a2[mi][1], a2[mi][2], a2[mi][3], ra + OFF_A2);
            }
#pragma unroll
            for (int ni = 0; ni < NG; ni++) {
                uint32_t rb = sb + OFF_B1 + (wn + ni * 16 + frow) * 128 + kc;
                LDSM_X4(b1[ni][0], b1[ni][1], b1[ni][2], b1[ni][3], rb);
                LDSM_X4(b2[ni][0], b2[ni][1], b2[ni][2], b2[ni][3], rb + BL);
            }
#pragma unroll
            for (int mi = 0; mi < 2; mi++)
#pragma unroll
                for (int nj = 0; nj < NJ; nj++)
                    MMA_S8(acc0[mi][nj], a1[mi], b1[nj >> 1][nj & 1], b1[nj >> 1][(nj & 1) + 2]);
#pragma unroll
            for (int mi = 0; mi < 2; mi++)
#pragma unroll
                for (int nj = 0; nj < NJ; nj++)
                    MMA_S8(acc1[mi][nj], a1[mi], b2[nj >> 1][nj & 1], b2[nj >> 1][(nj & 1) + 2]);
#pragma unroll
            for (int mi = 0; mi < 2; mi++)
#pragma unroll
                for (int nj = 0; nj < NJ; nj++)
                    MMA_S8(acc1[mi][nj], a2[mi], b1[nj >> 1][nj & 1], b1[nj >> 1][(nj & 1) + 2]);
        }
    }

    const int gr = lane >> 2, gc = lane & 3;
    const bool second = DUAL && (m0 >= Dm);
#pragma unroll
    for (int mi = 0; mi < 2; mi++) {
#pragma unroll
        for (int half = 0; half < 2; half++) {
            const int m = m0 + wm + mi * 16 + gr + half * 8;
            const int mrow = second ? (m - Dm) : m;
            const float sa = sA[m];
            float bm = 0.0f;
            if ((EPI == 1 || EPI == 2) && BIASROW) bm = bias[m];
#pragma unroll
            for (int nj = 0; nj < NJ; nj++) {
                const int n = n0 + wn + nj * 8 + 2 * gc;
                float v0 = sa * sB[n] * ((float)acc0[mi][nj][half * 2 + 0] +
                                         (float)acc1[mi][nj][half * 2 + 0] * (1.0f / 256.0f));
                float v1 = sa * sB[n + 1] * ((float)acc0[mi][nj][half * 2 + 1] +
                                             (float)acc1[mi][nj][half * 2 + 1] * (1.0f / 256.0f));
                if (EPI == 1 || EPI == 2) {
                    if (BIASROW) { v0 += bm; v1 += bm; }
                    else         { v0 += bias[n]; v1 += bias[n + 1]; }
                }
                if (EPI == 2 || (DUAL && second)) {
                    v0 *= sigmoidf_(v0); v1 *= sigmoidf_(v1);
                }
                if (EPI == 3) {
                    v0 = fmaxf(v0, 0.0f) + log1pf(expf(-fabsf(v0)));
                    v1 = fmaxf(v1, 0.0f) + log1pf(expf(-fabsf(v1)));
                }
                size_t idx = (size_t)mrow * Nn + n;
                float* dst = (DUAL && second) ? Cf2 : Cf;
                *(float2*)&dst[idx] = make_float2(v0, v1);
            }
        }
    }
}

// ---------------- B/C projections -------------------------------------------
__global__ void __launch_bounds__(256) bc_kernel(const float* __restrict__ Xc,
                                                 const float* __restrict__ WB,
                                                 const float* __restrict__ WC,
                                                 float* __restrict__ Bo,
                                                 float* __restrict__ Co) {
    __shared__ float row[Dm];
    const int l = blockIdx.x;
    for (int k = threadIdx.x; k < Dm; k += 256) row[k] = Xc[(size_t)l * Dm + k];
    __syncthreads();
    const int part = threadIdx.x & 7;
    const int out = threadIdx.x >> 3;
    const int n = out & 15;
    const float* W = (out < 16) ? WB : WC;
    float s = 0.0f;
    for (int k = part; k < Dm; k += 8) s = fmaf(row[k], W[k * Ns + n], s);
#pragma unroll
    for (int off = 4; off; off >>= 1) s += __shfl_down_sync(0xffffffffu, s, off, 8);
    if (part == 0) {
        if (out < 16) Bo[l * Ns + n] = s;
        else          Co[l * Ns + n] = s;
    }
}

// ---------------- selective scan v5 (smem-staged, fp32 out) -------------------
constexpr int SCH = 64;
constexpr int SNC = Dm / SCH;

__global__ void __launch_bounds__(128) scan_kernel(const float* __restrict__ delta,
                                                   const float* __restrict__ Xc,
                                                   const float* __restrict__ Bm,
                                                   const float* __restrict__ Cm,
                                                   const float* __restrict__ Alog,
                                                   float* __restrict__ Y) {
    __shared__ float sD[2][SCH][8];
    __shared__ float sX[2][SCH][8];
    __shared__ float sB[2][SCH][16];
    __shared__ float sC[2][SCH][16];

    const int tid = threadIdx.x;
    const int n = tid & 15;
    const int dl = tid >> 4;
    const int d0 = blockIdx.x * 8;
    const int d = d0 + dl;
    const float a = -expf(Alog[d * Ns + n]);

    auto load_chunk = [&](int c) {
        const int buf = c & 1;
        const int l0 = c * SCH;
        {
            int j = tid >> 1, hq = tid & 1;
            const size_t src = (size_t)(l0 + j) * Dm + d0 + hq * 4;
            cpa16(smem_u32(&sD[buf][j][hq * 4]), delta + src);
            cpa16(smem_u32(&sX[buf][j][hq * 4]), Xc + src);
        }
#pragma unroll
        for (int i = 0; i < 2; i++) {
            int task = tid + i * 128;
            int j = task >> 2, q = task & 3;
            cpa16(smem_u32(&sB[buf][j][q * 4]), Bm + (size_t)(l0 + j) * Ns + q * 4);
            cpa16(smem_u32(&sC[buf][j][q * 4]), Cm + (size_t)(l0 + j) * Ns + q * 4);
        }
        asm volatile("cp.async.commit_group;" ::: "memory");
    };

    load_chunk(0);
    float h = 0.0f;

    for (int c = 0; c < SNC; c++) {
        const int buf = c & 1;
        if (c + 1 < SNC) {
            load_chunk(c + 1);
            asm volatile("cp.async.wait_group 1;" ::: "memory");
        } else {
            asm volatile("cp.async.wait_group 0;" ::: "memory");
        }
        __syncthreads();

#pragma unroll 4
        for (int j = 0; j < SCH; j++) {
            float de = sD[buf][j][dl];
            float xv = sX[buf][j][dl];
            float bv = sB[buf][j][n];
            float cv = sC[buf][j][n];
            float e = __expf(de * a);
            h = fmaf(e, h, de * xv * bv);
            float pr = h * cv;
#pragma unroll
            for (int off = 8; off; off >>= 1)
                pr += __shfl_down_sync(0xffffffffu, pr, off, 16);
            if (n == 0)
                Y[(size_t)(c * SCH + j) * Dm + d] = pr;
        }
        __syncthreads();
    }
}

// ---------------- launch ------------------------------------------------------
extern "C" void kernel_launch(void* const* d_in, const int* in_sizes, int n_in,
                              void* d_out, int out_size) {
    const float* x    = (const float*)d_in[0];
    const float* Wp   = (const float*)d_in[1];
    const float* bp   = (const float*)d_in[2];
    const float* cw   = (const float*)d_in[3];
    const float* cb   = (const float*)d_in[4];
    const float* Alog = (const float*)d_in[5];
    const float* Wd   = (const float*)d_in[6];
    const float* WB   = (const float*)d_in[7];
    const float* WC   = (const float*)d_in[8];
    float* out = (float*)d_out;

    int8_t *xq1, *xq2, *Wpq1, *Wpq2, *cwq1, *cwq2, *WdTq1, *WdTq2;
    int8_t *cBq1, *cBq2, *xcq1, *xcq2, *yq1, *yq2, *xgq1, *xgq2, *tq1, *tq2;
    float *WdTf, *p0, *xgf, *xc, *del, *yf, *tf, *Bm, *Cm, *colmax;
    float *scx, *scWp, *sccw, *scWdT, *scCB, *scxc, *scy, *scxg, *sct;
    cudaGetSymbolAddress((void**)&xq1, g_xq1);     cudaGetSymbolAddress((void**)&xq2, g_xq2);
    cudaGetSymbolAddress((void**)&Wpq1, g_Wpq1);   cudaGetSymbolAddress((void**)&Wpq2, g_Wpq2);
    cudaGetSymbolAddress((void**)&cwq1, g_cwq1);   cudaGetSymbolAddress((void**)&cwq2, g_cwq2);
    cudaGetSymbolAddress((void**)&WdTq1, g_WdTq1); cudaGetSymbolAddress((void**)&WdTq2, g_WdTq2);
    cudaGetSymbolAddress((void**)&cBq1, g_cBq1);   cudaGetSymbolAddress((void**)&cBq2, g_cBq2);
    cudaGetSymbolAddress((void**)&xcq1, g_xcq1);   cudaGetSymbolAddress((void**)&xcq2, g_xcq2);
    cudaGetSymbolAddress((void**)&yq1, g_yq1);     cudaGetSymbolAddress((void**)&yq2, g_yq2);
    cudaGetSymbolAddress((void**)&xgq1, g_xgq1);   cudaGetSymbolAddress((void**)&xgq2, g_xgq2);
    cudaGetSymbolAddress((void**)&tq1, g_tq1);     cudaGetSymbolAddress((void**)&tq2, g_tq2);
    cudaGetSymbolAddress((void**)&WdTf, g_WdTf);
    cudaGetSymbolAddress((void**)&p0, g_p0);
    cudaGetSymbolAddress((void**)&xgf, g_xgf);
    cudaGetSymbolAddress((void**)&xc, g_xc);
    cudaGetSymbolAddress((void**)&del, g_delta);
    cudaGetSymbolAddress((void**)&yf, g_yf);
    cudaGetSymbolAddress((void**)&tf, g_tf);
    cudaGetSymbolAddress((void**)&Bm, g_Bm);
    cudaGetSymbolAddress((void**)&Cm, g_Cm);
    cudaGetSymbolAddress((void**)&colmax, g_colmax);
    cudaGetSymbolAddress((void**)&scx, g_scx);     cudaGetSymbolAddress((void**)&scWp, g_scWp);
    cudaGetSymbolAddress((void**)&sccw, g_sccw);   cudaGetSymbolAddress((void**)&scWdT, g_scWdT);
    cudaGetSymbolAddress((void**)&scCB, g_scCB);   cudaGetSymbolAddress((void**)&scxc, g_scxc);
    cudaGetSymbolAddress((void**)&scy, g_scy);     cudaGetSymbolAddress((void**)&scxg, g_scxg);
    cudaGetSymbolAddress((void**)&sct, g_sct);

    const int SMEM = 4 * 49152;
    cudaFuncSetAttribute(gemm_i8<1, false, true>,  cudaFuncAttributeMaxDynamicSharedMemorySize, SMEM);
    cudaFuncSetAttribute(gemm_i8<2, true,  false>, cudaFuncAttributeMaxDynamicSharedMemorySize, SMEM);
    cudaFuncSetAttribute(gemm_i8<3, false, false>, cudaFuncAttributeMaxDynamicSharedMemorySize, SMEM);
    cudaFuncSetAttribute(gemm_i8<0, false, false>, cudaFuncAttributeMaxDynamicSharedMemorySize, SMEM);
    cudaFuncSetAttribute(gemm_i8<1, false, false>, cudaFuncAttributeMaxDynamicSharedMemorySize, SMEM);

    // #1: quantize x/Wp/cw, transpose Wd, init colmax
    prep_fused<<<5121, 256>>>(x, xq1, xq2, scx, Wp, Wpq1, Wpq2, scWp,
                              cw, cwq1, cwq2, sccw, Wd, WdTf, colmax);
    // #2: quantize WdT
    quant_g1024<<<Dm, 256>>>(WdTf, WdTq1, WdTq2, scWdT);

    // #3: fused input projections (int8): p0 + xg(silu), M=2048
    gemm_i8<1, false, true><<<dim3(16, 16), 256, SMEM>>>(
        xq1, xq2, Wpq1, Wpq2, scx, scWp, bp, p0, xgf, Dm, Dm);

    // #4: p0 column max; #5: conv B build (quantized)
    colmax_k<<<32, 256>>>(p0, colmax);
    conv_b_q<<<dim3(32, 32), 256>>>(p0, colmax, cBq1, cBq2, scCB);

    // #6: conv GEMM (int8, K=3072): xc = silu(conv + cb)
    gemm_i8<2, true, false><<<dim3(16, 8), 256, SMEM>>>(
        cwq1, cwq2, cBq1, cBq2, sccw, scCB, cb, xc, nullptr, Dm, KC);

    // #7: quantize xc
    quant_g1024<<<Dm, 256>>>(xc, xcq1, xcq2, scxc);

    // #8: delta = softplus(xc @ WdT) (int8)
    gemm_i8<3, false, false><<<dim3(16, 8), 256, SMEM>>>(
        xcq1, xcq2, WdTq1, WdTq2, scxc, scWdT, nullptr, del, nullptr, Dm, Dm);

    // #9-10: B/C projections + scan
    bc_kernel<<<Dm, 256>>>(xc, WB, WC, Bm, Cm);
    scan_kernel<<<Dm / 8, 128>>>(del, xc, Bm, Cm, Alog, yf);

    // #11-12: quantize y, xg
    quant_g1024<<<Dm, 256>>>(yf, yq1, yq2, scy);
    quant_g1024<<<Dm, 256>>>(xgf, xgq1, xgq2, scxg);

    // #13: t = y @ xg^T (int8)
    gemm_i8<0, false, false><<<dim3(16, 8), 256, SMEM>>>(
        yq1, yq2, xgq1, xgq2, scy, scxg, nullptr, tf, nullptr, Dm, Dm);

    // #14: quantize t
    quant_g1024<<<Dm, 256>>>(tf, tq1, tq2, sct);

    // #15: out = t @ Wp^T + b (int8)
    gemm_i8<1, false, false><<<dim3(16, 8), 256, SMEM>>>(
        tq1, tq2, Wpq1, Wpq2, sct, scWp, bp, out, nullptr, Dm, Dm);
}

// round 16
// speedup vs baseline: 1.4105x; 1.4105x over previous
#include <cuda_runtime.h>
#include <cuda_bf16.h>
#include <math.h>
#include <stdint.h>

constexpr int Dm = 1024;   // dim == seq len L
constexpr int Ns = 16;     // SSM state size
constexpr int KC = 3 * Dm; // conv GEMM K = 3072

typedef __nv_bfloat16 bf16;

// ---------------- scratch (static device globals: allocation-free) ----------
__device__ bf16 g_xhi[2 * Dm * Dm], g_xlo[2 * Dm * Dm];
__device__ bf16 g_Wphi[Dm * Dm],   g_Wplo[Dm * Dm];
__device__ bf16 g_cwhi[Dm * KC],   g_cwlo[Dm * KC];
__device__ bf16 g_cBhi[Dm * KC],   g_cBlo[Dm * KC];
__device__ float  g_WdTf[Dm * Dm];
__device__ int8_t g_WdTq1[Dm * Dm], g_WdTq2[Dm * Dm];
__device__ int8_t g_Wpq1[Dm * Dm],  g_Wpq2[Dm * Dm];
__device__ int8_t g_xcq1[Dm * Dm],  g_xcq2[Dm * Dm];
__device__ int8_t g_yq1[Dm * Dm],   g_yq2[Dm * Dm];
__device__ int8_t g_xgq1[Dm * Dm],  g_xgq2[Dm * Dm];
__device__ int8_t g_tq1[Dm * Dm],   g_tq2[Dm * Dm];
__device__ float g_p0[Dm * Dm];
__device__ float g_xgf[Dm * Dm];
__device__ float g_xc[Dm * Dm];
__device__ float g_delta[Dm * Dm];
__device__ float g_yf[Dm * Dm];
__device__ float g_tf[Dm * Dm];
__device__ float g_Bm[Dm * Ns], g_Cm[Dm * Ns];
__device__ float g_scWp[Dm], g_scWdT[Dm], g_scxc[Dm];
__device__ float g_scy[Dm], g_scxg[Dm], g_sct[Dm];

__device__ __forceinline__ float sigmoidf_(float x) {
    return 1.0f / (1.0f + expf(-x));
}

__device__ __forceinline__ uint32_t smem_u32(const void* p) {
    uint32_t a;
    asm("{ .reg .u64 t; cvta.to.shared.u64 t, %1; cvt.u32.u64 %0, t; }" : "=r"(a) : "l"(p));
    return a;
}

#define SWZ(x) ((x) ^ (((x) >> 3) & 0x70))

__device__ __forceinline__ void cpa16(uint32_t dst, const void* src) {
    asm volatile("cp.async.cg.shared.global [%0], [%1], 16;" :: "r"(dst), "l"(src));
}

#define MMA_BF16(c, a, b0, b1)                                                   \
    asm volatile(                                                                \
        "mma.sync.aligned.m16n8k16.row.col.f32.bf16.bf16.f32 "                   \
        "{%0,%1,%2,%3},{%4,%5,%6,%7},{%8,%9},{%0,%1,%2,%3};"                     \
        : "+f"(c[0]), "+f"(c[1]), "+f"(c[2]), "+f"(c[3])                         \
        : "r"(a[0]), "r"(a[1]), "r"(a[2]), "r"(a[3]), "r"(b0), "r"(b1))

#define MMA_S8(c, a, b0, b1)                                                     \
    asm volatile(                                                                \
        "mma.sync.aligned.m16n8k32.row.col.s32.s8.s8.s32 "                       \
        "{%0,%1,%2,%3},{%4,%5,%6,%7},{%8,%9},{%0,%1,%2,%3};"                     \
        : "+r"(c[0]), "+r"(c[1]), "+r"(c[2]), "+r"(c[3])                         \
        : "r"(a[0]), "r"(a[1]), "r"(a[2]), "r"(a[3]), "r"(b0), "r"(b1))

#define LDSM_X4(r0, r1, r2, r3, addr)                                            \
    asm volatile("ldmatrix.sync.aligned.m8n8.x4.shared.b16 {%0,%1,%2,%3}, [%4];" \
        : "=r"(r0), "=r"(r1), "=r"(r2), "=r"(r3) : "r"(addr))

// ---------------- block max + two-level int8 quant ---------------------------
__device__ __forceinline__ float block_max(float m, float* red) {
    const int tid = threadIdx.x;
#pragma unroll
    for (int off = 16; off; off >>= 1)
        m = fmaxf(m, __shfl_xor_sync(0xffffffffu, m, off));
    if ((tid & 31) == 0) red[tid >> 5] = m;
    __syncthreads();
    if (tid < 32) {
        float t = (tid < 8) ? red[tid] : 0.0f;
#pragma unroll
        for (int off = 4; off; off >>= 1)
            t = fmaxf(t, __shfl_xor_sync(0xffffffffu, t, off));
        if (tid == 0) red[0] = t;
    }
    __syncthreads();
    return red[0];
}

__device__ __forceinline__ void quant_row_dev(const float* __restrict__ rp,
                                              int8_t* __restrict__ q1,
                                              int8_t* __restrict__ q2,
                                              float* __restrict__ scOut,
                                              float* red) {
    const int tid = threadIdx.x;
    float4 v = ((const float4*)rp)[tid];
    float m = fmaxf(fmaxf(fabsf(v.x), fabsf(v.y)), fmaxf(fabsf(v.z), fabsf(v.w)));
    float mx = fmaxf(block_max(m, red), 1e-20f);
    float inv = 127.0f / mx;
    if (tid == 0) *scOut = mx * (1.0f / 127.0f);
    float f[4] = {v.x * inv, v.y * inv, v.z * inv, v.w * inv};
    char c1[4], c2[4];
#pragma unroll
    for (int j = 0; j < 4; j++) {
        float a = rintf(f[j]);
        float b = fminf(fmaxf(rintf((f[j] - a) * 256.0f), -127.0f), 127.0f);
        c1[j] = (char)(int)a;
        c2[j] = (char)(int)b;
    }
    ((int*)q1)[tid] = *(int*)c1;
    ((int*)q2)[tid] = *(int*)c2;
}

__global__ void __launch_bounds__(256) quant_g1024(const float* __restrict__ in,
                                                   int8_t* __restrict__ q1,
                                                   int8_t* __restrict__ q2,
                                                   float* __restrict__ sc) {
    __shared__ float red[8];
    const size_t off = (size_t)blockIdx.x * Dm;
    quant_row_dev(in + off, q1 + off, q2 + off, &sc[blockIdx.x], red);
}

// ---------------- fused prep -------------------------------------------------
// [0,1024) x-split, [1024,1536) Wp-split, [1536,3072) cw-split,
// [3072,4096) Wd transpose -> fp32, [4096,5120) Wp int8-quant
__device__ __forceinline__ void split_body(const float* __restrict__ in,
                                           bf16* __restrict__ hi,
                                           bf16* __restrict__ lo,
                                           int blk) {
    int i = (blk * 256 + threadIdx.x) * 8;
    float4 v0 = *(const float4*)(in + i);
    float4 v1 = *(const float4*)(in + i + 4);
    float vv[8] = {v0.x, v0.y, v0.z, v0.w, v1.x, v1.y, v1.z, v1.w};
    __nv_bfloat162 hb[4], lb[4];
#pragma unroll
    for (int j = 0; j < 4; j++) {
        bf16 h0 = __float2bfloat16(vv[2 * j]);
        bf16 h1 = __float2bfloat16(vv[2 * j + 1]);
        hb[j].x = h0; hb[j].y = h1;
        lb[j].x = __float2bfloat16(vv[2 * j] - __bfloat162float(h0));
        lb[j].y = __float2bfloat16(vv[2 * j + 1] - __bfloat162float(h1));
    }
    *(int4*)(hi + i) = *(int4*)hb;
    *(int4*)(lo + i) = *(int4*)lb;
}

__global__ void __launch_bounds__(256) prep_fused(
    const float* __restrict__ x,  bf16* __restrict__ xhi,  bf16* __restrict__ xlo,
    const float* __restrict__ Wp, bf16* __restrict__ Wphi, bf16* __restrict__ Wplo,
    const float* __restrict__ cw, bf16* __restrict__ cwhi, bf16* __restrict__ cwlo,
    const float* __restrict__ Wd, float* __restrict__ WdTf,
    int8_t* __restrict__ Wpq1, int8_t* __restrict__ Wpq2, float* __restrict__ scWp)
{
    __shared__ float red[8];
    __shared__ float t[32][33];
    const int b = blockIdx.x;
    if (b < 1024) {
        split_body(x, xhi, xlo, b);
    } else if (b < 1536) {
        split_body(Wp, Wphi, Wplo, b - 1024);
    } else if (b < 3072) {
        split_body(cw, cwhi, cwlo, b - 1536);
    } else if (b < 4096) {
        int bi = b - 3072;
        int x0 = (bi & 31) * 32, y0 = (bi >> 5) * 32;
        int tx = threadIdx.x & 31, ty0 = threadIdx.x >> 5;
        for (int j = ty0; j < 32; j += 8)
            t[j][tx] = Wd[(y0 + j) * Dm + x0 + tx];
        __syncthreads();
        for (int j = ty0; j < 32; j += 8)
            WdTf[(size_t)(x0 + j) * Dm + y0 + tx] = t[tx][j];
    } else {
        const size_t off = (size_t)(b - 4096) * Dm;
        quant_row_dev(Wp + off, Wpq1 + off, Wpq2 + off, &scWp[b - 4096], red);
    }
}

// ---------------- conv B build (bf16 split, round-14) -------------------------
__global__ void __launch_bounds__(256) conv_b_build(const float* __restrict__ P0,
                                                    bf16* __restrict__ hi,
                                                    bf16* __restrict__ lo) {
    __shared__ float Xs[32][35];
    int d0 = blockIdx.x * 32, i0 = blockIdx.y * 32;
    int tid = threadIdx.x;
    for (int idx = tid; idx < 32 * 34; idx += 256) {
        int r = idx / 34, c = idx % 34;
        int gd = d0 - 1 + c;
        Xs[r][c] = (gd >= 0 && gd < Dm) ? P0[(size_t)(i0 + r) * Dm + gd] : 0.0f;
    }
    __syncthreads();
    int i = tid & 31;
    for (int dl = tid >> 5; dl < 32; dl += 8) {
        size_t base = (size_t)(d0 + dl) * KC + (size_t)(i0 + i) * 3;
#pragma unroll
        for (int kk = 0; kk < 3; kk++) {
            float x = Xs[i][dl + kk];
            bf16 h = __float2bfloat16(x);
            hi[base + kk] = h;
            lo[base + kk] = __float2bfloat16(x - __bfloat162float(h));
        }
    }
}

// ---------------- bf16-split HMMA GEMM (round-14 core) ------------------------
template <int NT, int TM, int TN, int EPI, bool BIASROW, bool WF32, bool WSPLIT,
          bool DUAL>
__global__ void __launch_bounds__(NT, 1)
gemm_mma(const bf16* __restrict__ Ah, const bf16* __restrict__ Al,
         const bf16* __restrict__ Bh, const bf16* __restrict__ Bl,
         const float* __restrict__ bias,
         float* __restrict__ Cf, bf16* __restrict__ Chi, bf16* __restrict__ Clo,
         float* __restrict__ Cf2,
         int Nn, int K)
{
    constexpr int OFF_AL = TM * 128;
    constexpr int OFF_BH = TM * 256;
    constexpr int BHL = TN * 128;
    constexpr int STAGEB = (TM + TN) * 256;
    constexpr int NBUF = (STAGEB >= 65536) ? 3 : 4;
    constexpr int DEPTH = NBUF - 1;
    constexpr int WARPS_M = TM / 32;
    constexpr int NWARP = NT / 32;
    constexpr int WN = TN / (NWARP / WARPS_M);
    constexpr int NG = WN / 16;
    constexpr int NJ = WN / 8;

    extern __shared__ __align__(1024) char dyns[];
    const int tid = threadIdx.x;
    const int lane = tid & 31, warp = tid >> 5;
    const int m0 = blockIdx.y * TM, n0 = blockIdx.x * TN;
    const uint32_t dbase = smem_u32(dyns);
    const int S = K >> 6;

    float acc[2][NJ][4];
#pragma unroll
    for (int a = 0; a < 2; a++)
#pragma unroll
        for (int b = 0; b < NJ; b++)
#pragma unroll
            for (int c = 0; c < 4; c++) acc[a][b][c] = 0.0f;

    auto load_stage = [&](int s) {
        const uint32_t sb = dbase + (s % NBUF) * STAGEB;
        const int k0 = s << 6;
#pragma unroll
        for (int i = 0; i < TM * 8 / NT; i++) {
            int q = tid + i * NT;
            int r = q >> 3, c = q & 7;
            uint32_t so = SWZ((uint32_t)(r * 128 + c * 16));
            size_t ga = (size_t)(m0 + r) * K + k0 + c * 8;
            cpa16(sb + so, Ah + ga);
            cpa16(sb + OFF_AL + so, Al + ga);
        }
#pragma unroll
        for (int i = 0; i < TN * 8 / NT; i++) {
            int q = tid + i * NT;
            int r = q >> 3, c = q & 7;
            uint32_t so = SWZ((uint32_t)(r * 128 + c * 16));
            size_t gb = (size_t)(n0 + r) * K + k0 + c * 8;
            cpa16(sb + OFF_BH + so, Bh + gb);
            cpa16(sb + OFF_BH + BHL + so, Bl + gb);
        }
        asm volatile("cp.async.commit_group;" ::: "memory");
    };

#pragma unroll
    for (int s = 0; s < DEPTH; s++) load_stage(s);

    const int wm = (warp % WARPS_M) * 32, wn = (warp / WARPS_M) * WN;
    const uint32_t frow = (lane & 7) + ((lane >> 3) & 1) * 8;
    const uint32_t fxor = (frow & 7) << 4;
    const uint32_t fcol = (lane >> 4) << 4;

    for (int s = 0; s < S; s++) {
        asm volatile("cp.async.wait_group %0;" :: "n"(DEPTH - 1) : "memory");
        __syncthreads();
        if (s + DEPTH < S) load_stage(s + DEPTH);
        else asm volatile("cp.async.commit_group;" ::: "memory");

        const uint32_t sb = dbase + (s % NBUF) * STAGEB;
#pragma unroll
        for (int ks = 0; ks < 4; ks++) {
            const uint32_t kc = (uint32_t)(ks * 32 + fcol) ^ fxor;
            uint32_t ahb[2][4], alb[2][4], bhb[NG][4], blb[NG][4];
#pragma unroll
            for (int mi = 0; mi < 2; mi++) {
                uint32_t ra = sb + (wm + mi * 16 + frow) * 128 + kc;
                LDSM_X4(ahb[mi][0], ahb[mi][1], ahb[mi][2], ahb[mi][3], ra);
                LDSM_X4(alb[mi][0], alb[mi][1], alb[mi][2], alb[mi][3], ra + OFF_AL);
            }
#pragma unroll
            for (int ni = 0; ni < NG; ni++) {
                uint32_t rb = sb + OFF_BH + (wn + ni * 16 + frow) * 128 + kc;
                LDSM_X4(bhb[ni][0], bhb[ni][1], bhb[ni][2], bhb[ni][3], rb);
                LDSM_X4(blb[ni][0], blb[ni][1], blb[ni][2], blb[ni][3], rb + BHL);
            }
#pragma unroll
            for (int mi = 0; mi < 2; mi++)
#pragma unroll
                for (int nj = 0; nj < NJ; nj++)
                    MMA_BF16(acc[mi][nj], ahb[mi], bhb[nj >> 1][nj & 1], bhb[nj >> 1][(nj & 1) + 2]);
#pragma unroll
            for (int mi = 0; mi < 2; mi++)
#pragma unroll
                for (int nj = 0; nj < NJ; nj++)
                    MMA_BF16(acc[mi][nj], ahb[mi], blb[nj >> 1][nj & 1], blb[nj >> 1][(nj & 1) + 2]);
#pragma unroll
            for (int mi = 0; mi < 2; mi++)
#pragma unroll
                for (int nj = 0; nj < NJ; nj++)
                    MMA_BF16(acc[mi][nj], alb[mi], bhb[nj >> 1][nj & 1], bhb[nj >> 1][(nj & 1) + 2]);
        }
    }

    const int gr = lane >> 2, gc = lane & 3;
    const bool second = DUAL && (m0 >= Dm);
#pragma unroll
    for (int mi = 0; mi < 2; mi++) {
#pragma unroll
        for (int half = 0; half < 2; half++) {
            const int m = m0 + wm + mi * 16 + gr + half * 8;
            const int mrow = second ? (m - Dm) : m;
            float bm = 0.0f;
            if ((EPI == 1 || EPI == 2) && BIASROW) bm = bias[m];
#pragma unroll
            for (int nj = 0; nj < NJ; nj++) {
                const int n = n0 + wn + nj * 8 + 2 * gc;
                float v0 = acc[mi][nj][half * 2 + 0];
                float v1 = acc[mi][nj][half * 2 + 1];
                if (EPI == 1 || EPI == 2) {
                    if (BIASROW) { v0 += bm; v1 += bm; }
                    else         { v0 += bias[n]; v1 += bias[n + 1]; }
                }
                if (EPI == 2 || (DUAL && second)) {
                    v0 *= sigmoidf_(v0); v1 *= sigmoidf_(v1);
                }
                if (EPI == 3) {
                    v0 = fmaxf(v0, 0.0f) + log1pf(expf(-fabsf(v0)));
                    v1 = fmaxf(v1, 0.0f) + log1pf(expf(-fabsf(v1)));
                }
                size_t idx = (size_t)mrow * Nn + n;
                if (DUAL && second) {
                    *(float2*)&Cf2[idx] = make_float2(v0, v1);
                } else {
                    if (WF32) *(float2*)&Cf[idx] = make_float2(v0, v1);
                    if (WSPLIT) {
                        bf16 h0 = __float2bfloat16(v0);
                        bf16 h1 = __float2bfloat16(v1);
                        __nv_bfloat162 hh; hh.x = h0; hh.y = h1;
                        __nv_bfloat162 ll;
                        ll.x = __float2bfloat16(v0 - __bfloat162float(h0));
                        ll.y = __float2bfloat16(v1 - __bfloat162float(h1));
                        *(__nv_bfloat162*)&Chi[idx] = hh;
                        *(__nv_bfloat162*)&Clo[idx] = ll;
                    }
                }
            }
        }
    }
}

// ---------------- int8 3-term IMMA GEMM (pilot-proven shape only) -------------
// K=1024, grid (16,8), 256 thr. EPI: 0 none, 1 +bias[n], 3 softplus.
template <int EPI>
__global__ void __launch_bounds__(256, 1)
gemm_i8(const int8_t* __restrict__ Aq1, const int8_t* __restrict__ Aq2,
        const int8_t* __restrict__ Bq1, const int8_t* __restrict__ Bq2,
        const float* __restrict__ sA, const float* __restrict__ sB,
        const float* __restrict__ bias,
        float* __restrict__ Cf, int Nn, int K)
{
    constexpr int TM = 128, TN = 64, NT = 256;
    constexpr int OFF_A2 = TM * 128;
    constexpr int OFF_B1 = TM * 256;
    constexpr int BL = TN * 128;
    constexpr int STAGEB = (TM + TN) * 256;
    constexpr int NBUF = 4, DEPTH = 3;
    constexpr int NJ = 4, NG = 2;

    extern __shared__ __align__(1024) char dyns[];
    const int tid = threadIdx.x;
    const int lane = tid & 31, warp = tid >> 5;
    const int m0 = blockIdx.y * TM, n0 = blockIdx.x * TN;
    const uint32_t dbase = smem_u32(dyns);
    const int S = K >> 7;

    int acc0[2][NJ][4], acc1[2][NJ][4];
#pragma unroll
    for (int a = 0; a < 2; a++)
#pragma unroll
        for (int b = 0; b < NJ; b++)
#pragma unroll
            for (int c = 0; c < 4; c++) { acc0[a][b][c] = 0; acc1[a][b][c] = 0; }

    auto load_stage = [&](int s) {
        const uint32_t sb = dbase + (s % NBUF) * STAGEB;
        const int k0 = s << 7;
#pragma unroll
        for (int i = 0; i < 4; i++) {
            int q = tid + i * NT;
            int r = q >> 3, c = q & 7;
            uint32_t so = SWZ((uint32_t)(r * 128 + c * 16));
            size_t ga = (size_t)(m0 + r) * K + k0 + c * 16;
            cpa16(sb + so, Aq1 + ga);
            cpa16(sb + OFF_A2 + so, Aq2 + ga);
        }
#pragma unroll
        for (int i = 0; i < 2; i++) {
            int q = tid + i * NT;
            int r = q >> 3, c = q & 7;
            uint32_t so = SWZ((uint32_t)(r * 128 + c * 16));
            size_t gb = (size_t)(n0 + r) * K + k0 + c * 16;
            cpa16(sb + OFF_B1 + so, Bq1 + gb);
            cpa16(sb + OFF_B1 + BL + so, Bq2 + gb);
        }
        asm volatile("cp.async.commit_group;" ::: "memory");
    };

#pragma unroll
    for (int s = 0; s < DEPTH; s++) load_stage(s);

    const int wm = (warp & 3) * 32, wn = (warp >> 2) * 32;
    const uint32_t frow = (lane & 7) + ((lane >> 3) & 1) * 8;
    const uint32_t fxor = (frow & 7) << 4;
    const uint32_t fcol = (lane >> 4) << 4;

    for (int s = 0; s < S; s++) {
        asm volatile("cp.async.wait_group %0;" :: "n"(DEPTH - 1) : "memory");
        __syncthreads();
        if (s + DEPTH < S) load_stage(s + DEPTH);
        else asm volatile("cp.async.commit_group;" ::: "memory");

        const uint32_t sb = dbase + (s % NBUF) * STAGEB;
#pragma unroll
        for (int ks = 0; ks < 4; ks++) {
            const uint32_t kc = (uint32_t)(ks * 32 + fcol) ^ fxor;
            uint32_t a1[2][4], a2[2][4], b1[NG][4], b2[NG][4];
#pragma unroll
            for (int mi = 0; mi < 2; mi++) {
                uint32_t ra = sb + (wm + mi * 16 + frow) * 128 + kc;
                LDSM_X4(a1[mi][0], a1[mi][1], a1[mi][2], a1[mi][3], ra);
                LDSM_X4(a2[mi][0], a2[mi][1], a2[mi][2], a2[mi][3], ra + OFF_A2);
            }
#pragma unroll
            for (int ni = 0; ni < NG; ni++) {
                uint32_t rb = sb + OFF_B1 + (wn + ni * 16 + frow) * 128 + kc;
                LDSM_X4(b1[ni][0], b1[ni][1], b1[ni][2], b1[ni][3], rb);
                LDSM_X4(b2[ni][0], b2[ni][1], b2[ni][2], b2[ni][3], rb + BL);
            }
#pragma unroll
            for (int mi = 0; mi < 2; mi++)
#pragma unroll
                for (int nj = 0; nj < NJ; nj++)
                    MMA_S8(acc0[mi][nj], a1[mi], b1[nj >> 1][nj & 1], b1[nj >> 1][(nj & 1) + 2]);
#pragma unroll
            for (int mi = 0; mi < 2; mi++)
#pragma unroll
                for (int nj = 0; nj < NJ; nj++)
                    MMA_S8(acc1[mi][nj], a1[mi], b2[nj >> 1][nj & 1], b2[nj >> 1][(nj & 1) + 2]);
#pragma unroll
            for (int mi = 0; mi < 2; mi++)
#pragma unroll
                for (int nj = 0; nj < NJ; nj++)
                    MMA_S8(acc1[mi][nj], a2[mi], b1[nj >> 1][nj & 1], b1[nj >> 1][(nj & 1) + 2]);
        }
    }

    const int gr = lane >> 2, gc = lane & 3;
#pragma unroll
    for (int mi = 0; mi < 2; mi++) {
#pragma unroll
        for (int half = 0; half < 2; half++) {
            const int m = m0 + wm + mi * 16 + gr + half * 8;
            const float sa = sA[m];
#pragma unroll
            for (int nj = 0; nj < NJ; nj++) {
                const int n = n0 + wn + nj * 8 + 2 * gc;
                float v0 = sa * sB[n] * ((float)acc0[mi][nj][half * 2 + 0] +
                                         (float)acc1[mi][nj][half * 2 + 0] * (1.0f / 256.0f));
                float v1 = sa * sB[n + 1] * ((float)acc0[mi][nj][half * 2 + 1] +
                                             (float)acc1[mi][nj][half * 2 + 1] * (1.0f / 256.0f));
                if (EPI == 1) { v0 += bias[n]; v1 += bias[n + 1]; }
                if (EPI == 3) {
                    v0 = fmaxf(v0, 0.0f) + log1pf(expf(-fabsf(v0)));
                    v1 = fmaxf(v1, 0.0f) + log1pf(expf(-fabsf(v1)));
                }
                *(float2*)&Cf[(size_t)m * Nn + n] = make_float2(v0, v1);
            }
        }
    }
}

// ---------------- B/C projections ---------------------------------------------
__global__ void __launch_bounds__(256) bc_kernel(const float* __restrict__ Xc,
                                                 const float* __restrict__ WB,
                                                 const float* __restrict__ WC,
                                                 float* __restrict__ Bo,
                                                 float* __restrict__ Co) {
    __shared__ float row[Dm];
    const int l = blockIdx.x;
    for (int k = threadIdx.x; k < Dm; k += 256) row[k] = Xc[(size_t)l * Dm + k];
    __syncthreads();
    const int part = threadIdx.x & 7;
    const int out = threadIdx.x >> 3;
    const int n = out & 15;
    const float* W = (out < 16) ? WB : WC;
    float s = 0.0f;
    for (int k = part; k < Dm; k += 8) s = fmaf(row[k], W[k * Ns + n], s);
#pragma unroll
    for (int off = 4; off; off >>= 1) s += __shfl_down_sync(0xffffffffu, s, off, 8);
    if (part == 0) {
        if (out < 16) Bo[l * Ns + n] = s;
        else          Co[l * Ns + n] = s;
    }
}

// ---------------- selective scan v5 (smem-staged, fp32 out) -------------------
constexpr int SCH = 64;
constexpr int SNC = Dm / SCH;

__global__ void __launch_bounds__(128) scan_kernel(const float* __restrict__ delta,
                                                   const float* __restrict__ Xc,
                                                   const float* __restrict__ Bm,
                                                   const float* __restrict__ Cm,
                                                   const float* __restrict__ Alog,
                                                   float* __restrict__ Y) {
    __shared__ float sD[2][SCH][8];
    __shared__ float sX[2][SCH][8];
    __shared__ float sB[2][SCH][16];
    __shared__ float sC[2][SCH][16];

    const int tid = threadIdx.x;
    const int n = tid & 15;
    const int dl = tid >> 4;
    const int d0 = blockIdx.x * 8;
    const int d = d0 + dl;
    const float a = -expf(Alog[d * Ns + n]);

    auto load_chunk = [&](int c) {
        const int buf = c & 1;
        const int l0 = c * SCH;
        {
            int j = tid >> 1, hq = tid & 1;
            const size_t src = (size_t)(l0 + j) * Dm + d0 + hq * 4;
            cpa16(smem_u32(&sD[buf][j][hq * 4]), delta + src);
            cpa16(smem_u32(&sX[buf][j][hq * 4]), Xc + src);
        }
#pragma unroll
        for (int i = 0; i < 2; i++) {
            int task = tid + i * 128;
            int j = task >> 2, q = task & 3;
            cpa16(smem_u32(&sB[buf][j][q * 4]), Bm + (size_t)(l0 + j) * Ns + q * 4);
            cpa16(smem_u32(&sC[buf][j][q * 4]), Cm + (size_t)(l0 + j) * Ns + q * 4);
        }
        asm volatile("cp.async.commit_group;" ::: "memory");
    };

    load_chunk(0);
    float h = 0.0f;

    for (int c = 0; c < SNC; c++) {
        const int buf = c & 1;
        if (c + 1 < SNC) {
            load_chunk(c + 1);
            asm volatile("cp.async.wait_group 1;" ::: "memory");
        } else {
            asm volatile("cp.async.wait_group 0;" ::: "memory");
        }
        __syncthreads();

#pragma unroll 4
        for (int j = 0; j < SCH; j++) {
            float de = sD[buf][j][dl];
            float xv = sX[buf][j][dl];
            float bv = sB[buf][j][n];
            float cv = sC[buf][j][n];
            float e = __expf(de * a);
            h = fmaf(e, h, de * xv * bv);
            float pr = h * cv;
#pragma unroll
            for (int off = 8; off; off >>= 1)
                pr += __shfl_down_sync(0xffffffffu, pr, off, 16);
            if (n == 0)
                Y[(size_t)(c * SCH + j) * Dm + d] = pr;
        }
        __syncthreads();
    }
}

// ---------------- launch ------------------------------------------------------
extern "C" void kernel_launch(void* const* d_in, const int* in_sizes, int n_in,
                              void* d_out, int out_size) {
    const float* x    = (const float*)d_in[0];
    const float* Wp   = (const float*)d_in[1];
    const float* bp   = (const float*)d_in[2];
    const float* cw   = (const float*)d_in[3];
    const float* cb   = (const float*)d_in[4];
    const float* Alog = (const float*)d_in[5];
    const float* Wd   = (const float*)d_in[6];
    const float* WB   = (const float*)d_in[7];
    const float* WC   = (const float*)d_in[8];
    float* out = (float*)d_out;

    bf16 *xhi, *xlo, *Wphi, *Wplo, *cwhi, *cwlo, *cBhi, *cBlo;
    int8_t *WdTq1, *WdTq2, *Wpq1, *Wpq2, *xcq1, *xcq2, *yq1, *yq2, *xgq1, *xgq2, *tq1, *tq2;
    float *WdTf, *p0, *xgf, *xc, *del, *yf, *tf, *Bm, *Cm;
    float *scWp, *scWdT, *scxc, *scy, *scxg, *sct;
    cudaGetSymbolAddress((void**)&xhi, g_xhi);     cudaGetSymbolAddress((void**)&xlo, g_xlo);
    cudaGetSymbolAddress((void**)&Wphi, g_Wphi);   cudaGetSymbolAddress((void**)&Wplo, g_Wplo);
    cudaGetSymbolAddress((void**)&cwhi, g_cwhi);   cudaGetSymbolAddress((void**)&cwlo, g_cwlo);
    cudaGetSymbolAddress((void**)&cBhi, g_cBhi);   cudaGetSymbolAddress((void**)&cBlo, g_cBlo);
    cudaGetSymbolAddress((void**)&WdTq1, g_WdTq1); cudaGetSymbolAddress((void**)&WdTq2, g_WdTq2);
    cudaGetSymbolAddress((void**)&Wpq1, g_Wpq1);   cudaGetSymbolAddress((void**)&Wpq2, g_Wpq2);
    cudaGetSymbolAddress((void**)&xcq1, g_xcq1);   cudaGetSymbolAddress((void**)&xcq2, g_xcq2);
    cudaGetSymbolAddress((void**)&yq1, g_yq1);     cudaGetSymbolAddress((void**)&yq2, g_yq2);
    cudaGetSymbolAddress((void**)&xgq1, g_xgq1);   cudaGetSymbolAddress((void**)&xgq2, g_xgq2);
    cudaGetSymbolAddress((void**)&tq1, g_tq1);     cudaGetSymbolAddress((void**)&tq2, g_tq2);
    cudaGetSymbolAddress((void**)&WdTf, g_WdTf);
    cudaGetSymbolAddress((void**)&p0, g_p0);
    cudaGetSymbolAddress((void**)&xgf, g_xgf);
    cudaGetSymbolAddress((void**)&xc, g_xc);
    cudaGetSymbolAddress((void**)&del, g_delta);
    cudaGetSymbolAddress((void**)&yf, g_yf);
    cudaGetSymbolAddress((void**)&tf, g_tf);
    cudaGetSymbolAddress((void**)&Bm, g_Bm);
    cudaGetSymbolAddress((void**)&Cm, g_Cm);
    cudaGetSymbolAddress((void**)&scWp, g_scWp);   cudaGetSymbolAddress((void**)&scWdT, g_scWdT);
    cudaGetSymbolAddress((void**)&scxc, g_scxc);   cudaGetSymbolAddress((void**)&scy, g_scy);
    cudaGetSymbolAddress((void**)&scxg, g_scxg);   cudaGetSymbolAddress((void**)&sct, g_sct);

    const int SMEM128 = 3 * 65536;
    const int SMEM64  = 4 * 49152;
    cudaFuncSetAttribute(gemm_mma<512, 128, 128, 1, false, true, false, true>,  cudaFuncAttributeMaxDynamicSharedMemorySize, SMEM128);
    cudaFuncSetAttribute(gemm_mma<256, 128, 64,  2, true,  true, false, false>, cudaFuncAttributeMaxDynamicSharedMemorySize, SMEM64);
    cudaFuncSetAttribute(gemm_i8<3>, cudaFuncAttributeMaxDynamicSharedMemorySize, SMEM64);
    cudaFuncSetAttribute(gemm_i8<0>, cudaFuncAttributeMaxDynamicSharedMemorySize, SMEM64);
    cudaFuncSetAttribute(gemm_i8<1>, cudaFuncAttributeMaxDynamicSharedMemorySize, SMEM64);

    // #1: prep (bf16 splits + Wd transpose fp32 + Wp int8 quant)
    prep_fused<<<5120, 256>>>(x, xhi, xlo, Wp, Wphi, Wplo, cw, cwhi, cwlo,
                              Wd, WdTf, Wpq1, Wpq2, scWp);
    // #2: quantize WdT
    quant_g1024<<<Dm, 256>>>(WdTf, WdTq1, WdTq2, scWdT);

    // #3: fused input projections (bf16): p0 fp32 + xg fp32 (silu)
    gemm_mma<512, 128, 128, 1, false, true, false, true><<<dim3(8, 16), 512, SMEM128>>>(
        xhi, xlo, Wphi, Wplo, bp, p0, nullptr, nullptr, xgf, Dm, Dm);

    // #4: conv B build (bf16)
    conv_b_build<<<dim3(32, 32), 256>>>(p0, cBhi, cBlo);

    // #5: conv GEMM (bf16, K=3072): xc fp32 only
    gemm_mma<256, 128, 64, 2, true, true, false, false><<<dim3(16, 8), 256, SMEM64>>>(
        cwhi, cwlo, cBhi, cBlo, cb, xc, nullptr, nullptr, nullptr, Dm, KC);

    // #6: quantize xc
    quant_g1024<<<Dm, 256>>>(xc, xcq1, xcq2, scxc);

    // #7: delta = softplus(xc @ WdT)  [int8]
    gemm_i8<3><<<dim3(16, 8), 256, SMEM64>>>(
        xcq1, xcq2, WdTq1, WdTq2, scxc, scWdT, nullptr, del, Dm, Dm);

    // #8-9: B/C projections + scan (fp32 y)
    bc_kernel<<<Dm, 256>>>(xc, WB, WC, Bm, Cm);
    scan_kernel<<<Dm / 8, 128>>>(del, xc, Bm, Cm, Alog, yf);

    // #10-11: quantize y and xg
    quant_g1024<<<Dm, 256>>>(yf, yq1, yq2, scy);
    quant_g1024<<<Dm, 256>>>(xgf, xgq1, xgq2, scxg);

    // #12: t = y @ xg^T  [int8] -> tf fp32
    gemm_i8<0><<<dim3(16, 8), 256, SMEM64>>>(
        yq1, yq2, xgq1, xgq2, scy, scxg, nullptr, tf, Dm, Dm);

    // #13: quantize t
    quant_g1024<<<Dm, 256>>>(tf, tq1, tq2, sct);

    // #14: out = t @ Wp^T + b  [int8]
    gemm_i8<1><<<dim3(16, 8), 256, SMEM64>>>(
        tq1, tq2, Wpq1, Wpq2, sct, scWp, bp, out, Dm, Dm);
}

// round 17
// speedup vs baseline: 1.7491x; 1.2401x over previous
#include <cuda_runtime.h>
#include <cuda_bf16.h>
#include <math.h>
#include <stdint.h>

constexpr int Dm = 1024;   // dim == seq len L
constexpr int Ns = 16;     // SSM state size
constexpr int KC = 3 * Dm; // conv GEMM K = 3072

typedef __nv_bfloat16 bf16;

// ---------------- scratch (static device globals: allocation-free) ----------
__device__ bf16 g_xhi[2 * Dm * Dm], g_xlo[2 * Dm * Dm];
__device__ bf16 g_Wphi[Dm * Dm],   g_Wplo[Dm * Dm];
__device__ bf16 g_cwhi[Dm * KC],   g_cwlo[Dm * KC];
__device__ bf16 g_WdThi[Dm * Dm],  g_WdTlo[Dm * Dm];
__device__ float g_p0[Dm * Dm];
__device__ float g_xgf[Dm * Dm];    // xg fp32 (for int8 quant)
__device__ bf16 g_cBhi[Dm * KC],   g_cBlo[Dm * KC];
__device__ float g_xc[Dm * Dm];
__device__ bf16 g_xchi[Dm * Dm],   g_xclo[Dm * Dm];
__device__ float g_delta[Dm * Dm];
__device__ float g_Bm[Dm * Ns], g_Cm[Dm * Ns];
__device__ float g_yf[Dm * Dm];     // y fp32 (for int8 quant)
__device__ int8_t g_yq1[Dm * Dm],  g_yq2[Dm * Dm];
__device__ int8_t g_xgq1[Dm * Dm], g_xgq2[Dm * Dm];
__device__ float g_scy[Dm], g_scxg[Dm];
__device__ bf16 g_thi[Dm * Dm],    g_tlo[Dm * Dm];

__device__ __forceinline__ float sigmoidf_(float x) {
    return 1.0f / (1.0f + expf(-x));
}

__device__ __forceinline__ uint32_t smem_u32(const void* p) {
    uint32_t a;
    asm("{ .reg .u64 t; cvta.to.shared.u64 t, %1; cvt.u32.u64 %0, t; }" : "=r"(a) : "l"(p));
    return a;
}

#define SWZ(x) ((x) ^ (((x) >> 3) & 0x70))

__device__ __forceinline__ void cpa16(uint32_t dst, const void* src) {
    asm volatile("cp.async.cg.shared.global [%0], [%1], 16;" :: "r"(dst), "l"(src));
}

#define MMA_BF16(c, a, b0, b1)                                                   \
    asm volatile(                                                                \
        "mma.sync.aligned.m16n8k16.row.col.f32.bf16.bf16.f32 "                   \
        "{%0,%1,%2,%3},{%4,%5,%6,%7},{%8,%9},{%0,%1,%2,%3};"                     \
        : "+f"(c[0]), "+f"(c[1]), "+f"(c[2]), "+f"(c[3])                         \
        : "r"(a[0]), "r"(a[1]), "r"(a[2]), "r"(a[3]), "r"(b0), "r"(b1))

#define MMA_S8(c, a, b0, b1)                                                     \
    asm volatile(                                                                \
        "mma.sync.aligned.m16n8k32.row.col.s32.s8.s8.s32 "                       \
        "{%0,%1,%2,%3},{%4,%5,%6,%7},{%8,%9},{%0,%1,%2,%3};"                     \
        : "+r"(c[0]), "+r"(c[1]), "+r"(c[2]), "+r"(c[3])                         \
        : "r"(a[0]), "r"(a[1]), "r"(a[2]), "r"(a[3]), "r"(b0), "r"(b1))

#define LDSM_X4(r0, r1, r2, r3, addr)                                            \
    asm volatile("ldmatrix.sync.aligned.m8n8.x4.shared.b16 {%0,%1,%2,%3}, [%4];" \
        : "=r"(r0), "=r"(r1), "=r"(r2), "=r"(r3) : "r"(addr))

// ---------------- fused prep ------------------------------------------------
__device__ __forceinline__ void split_body(const float* __restrict__ in,
                                           bf16* __restrict__ hi,
                                           bf16* __restrict__ lo,
                                           int blk) {
    int i = (blk * 256 + threadIdx.x) * 8;
    float4 v0 = *(const float4*)(in + i);
    float4 v1 = *(const float4*)(in + i + 4);
    float vv[8] = {v0.x, v0.y, v0.z, v0.w, v1.x, v1.y, v1.z, v1.w};
    __nv_bfloat162 hb[4], lb[4];
#pragma unroll
    for (int j = 0; j < 4; j++) {
        bf16 h0 = __float2bfloat16(vv[2 * j]);
        bf16 h1 = __float2bfloat16(vv[2 * j + 1]);
        hb[j].x = h0; hb[j].y = h1;
        lb[j].x = __float2bfloat16(vv[2 * j] - __bfloat162float(h0));
        lb[j].y = __float2bfloat16(vv[2 * j + 1] - __bfloat162float(h1));
    }
    *(int4*)(hi + i) = *(int4*)hb;
    *(int4*)(lo + i) = *(int4*)lb;
}

__global__ void __launch_bounds__(256) prep_fused(
    const float* __restrict__ x,  bf16* __restrict__ xhi,  bf16* __restrict__ xlo,
    const float* __restrict__ Wp, bf16* __restrict__ Wphi, bf16* __restrict__ Wplo,
    const float* __restrict__ Wd, bf16* __restrict__ WdThi, bf16* __restrict__ WdTlo,
    const float* __restrict__ cw, bf16* __restrict__ cwhi, bf16* __restrict__ cwlo)
{
    const int b = blockIdx.x;
    if (b < 1024) {
        split_body(x, xhi, xlo, b);
    } else if (b < 1536) {
        split_body(Wp, Wphi, Wplo, b - 1024);
    } else if (b < 2560) {
        __shared__ float t[32][33];
        int bi = b - 1536;
        int x0 = (bi & 31) * 32, y0 = (bi >> 5) * 32;
        int tx = threadIdx.x & 31, ty0 = threadIdx.x >> 5;
        for (int j = ty0; j < 32; j += 8)
            t[j][tx] = Wd[(y0 + j) * Dm + x0 + tx];
        __syncthreads();
        for (int j = ty0; j < 32; j += 8) {
            float v = t[tx][j];
            bf16 h = __float2bfloat16(v);
            size_t idx = (size_t)(x0 + j) * Dm + y0 + tx;
            WdThi[idx] = h;
            WdTlo[idx] = __float2bfloat16(v - __bfloat162float(h));
        }
    } else {
        split_body(cw, cwhi, cwlo, b - 2560);
    }
}

// ---------------- build conv B matrix ---------------------------------------
__global__ void __launch_bounds__(256) conv_b_build(const float* __restrict__ P0,
                                                    bf16* __restrict__ hi,
                                                    bf16* __restrict__ lo) {
    __shared__ float Xs[32][35];
    int d0 = blockIdx.x * 32, i0 = blockIdx.y * 32;
    int tid = threadIdx.x;
    for (int idx = tid; idx < 32 * 34; idx += 256) {
        int r = idx / 34, c = idx % 34;
        int gd = d0 - 1 + c;
        Xs[r][c] = (gd >= 0 && gd < Dm) ? P0[(size_t)(i0 + r) * Dm + gd] : 0.0f;
    }
    __syncthreads();
    int i = tid & 31;
    for (int dl = tid >> 5; dl < 32; dl += 8) {
        size_t base = (size_t)(d0 + dl) * KC + (size_t)(i0 + i) * 3;
#pragma unroll
        for (int kk = 0; kk < 3; kk++) {
            float x = Xs[i][dl + kk];
            bf16 h = __float2bfloat16(x);
            hi[base + kk] = h;
            lo[base + kk] = __float2bfloat16(x - __bfloat162float(h));
        }
    }
}

// ---------------- bf16-split HMMA GEMM (unchanged core) ----------------------
template <int NT, int TM, int TN, int EPI, bool BIASROW, bool WF32, bool WSPLIT,
          bool DUAL>
__global__ void __launch_bounds__(NT, 1)
gemm_mma(const bf16* __restrict__ Ah, const bf16* __restrict__ Al,
         const bf16* __restrict__ Bh, const bf16* __restrict__ Bl,
         const float* __restrict__ bias,
         float* __restrict__ Cf, bf16* __restrict__ Chi, bf16* __restrict__ Clo,
         float* __restrict__ Cf2,
         int Nn, int K)
{
    constexpr int OFF_AL = TM * 128;
    constexpr int OFF_BH = TM * 256;
    constexpr int BHL = TN * 128;
    constexpr int STAGEB = (TM + TN) * 256;
    constexpr int NBUF = (STAGEB >= 65536) ? 3 : 4;
    constexpr int DEPTH = NBUF - 1;
    constexpr int WARPS_M = TM / 32;
    constexpr int NWARP = NT / 32;
    constexpr int WN = TN / (NWARP / WARPS_M);
    constexpr int NG = WN / 16;
    constexpr int NJ = WN / 8;

    extern __shared__ __align__(1024) char dyns[];
    const int tid = threadIdx.x;
    const int lane = tid & 31, warp = tid >> 5;
    const int m0 = blockIdx.y * TM, n0 = blockIdx.x * TN;
    const uint32_t dbase = smem_u32(dyns);
    const int S = K >> 6;

    float acc[2][NJ][4];
#pragma unroll
    for (int a = 0; a < 2; a++)
#pragma unroll
        for (int b = 0; b < NJ; b++)
#pragma unroll
            for (int c = 0; c < 4; c++) acc[a][b][c] = 0.0f;

    auto load_stage = [&](int s) {
        const uint32_t sb = dbase + (s % NBUF) * STAGEB;
        const int k0 = s << 6;
#pragma unroll
        for (int i = 0; i < TM * 8 / NT; i++) {
            int q = tid + i * NT;
            int r = q >> 3, c = q & 7;
            uint32_t so = SWZ((uint32_t)(r * 128 + c * 16));
            size_t ga = (size_t)(m0 + r) * K + k0 + c * 8;
            cpa16(sb + so, Ah + ga);
            cpa16(sb + OFF_AL + so, Al + ga);
        }
#pragma unroll
        for (int i = 0; i < TN * 8 / NT; i++) {
            int q = tid + i * NT;
            int r = q >> 3, c = q & 7;
            uint32_t so = SWZ((uint32_t)(r * 128 + c * 16));
            size_t gb = (size_t)(n0 + r) * K + k0 + c * 8;
            cpa16(sb + OFF_BH + so, Bh + gb);
            cpa16(sb + OFF_BH + BHL + so, Bl + gb);
        }
        asm volatile("cp.async.commit_group;" ::: "memory");
    };

#pragma unroll
    for (int s = 0; s < DEPTH; s++) load_stage(s);

    const int wm = (warp % WARPS_M) * 32, wn = (warp / WARPS_M) * WN;
    const uint32_t frow = (lane & 7) + ((lane >> 3) & 1) * 8;
    const uint32_t fxor = (frow & 7) << 4;
    const uint32_t fcol = (lane >> 4) << 4;

    for (int s = 0; s < S; s++) {
        asm volatile("cp.async.wait_group %0;" :: "n"(DEPTH - 1) : "memory");
        __syncthreads();
        if (s + DEPTH < S) load_stage(s + DEPTH);
        else asm volatile("cp.async.commit_group;" ::: "memory");

        const uint32_t sb = dbase + (s % NBUF) * STAGEB;
#pragma unroll
        for (int ks = 0; ks < 4; ks++) {
            const uint32_t kc = (uint32_t)(ks * 32 + fcol) ^ fxor;
            uint32_t ahb[2][4], alb[2][4], bhb[NG][4], blb[NG][4];
#pragma unroll
            for (int mi = 0; mi < 2; mi++) {
                uint32_t ra = sb + (wm + mi * 16 + frow) * 128 + kc;
                LDSM_X4(ahb[mi][0], ahb[mi][1], ahb[mi][2], ahb[mi][3], ra);
                LDSM_X4(alb[mi][0], alb[mi][1], alb[mi][2], alb[mi][3], ra + OFF_AL);
            }
#pragma unroll
            for (int ni = 0; ni < NG; ni++) {
                uint32_t rb = sb + OFF_BH + (wn + ni * 16 + frow) * 128 + kc;
                LDSM_X4(bhb[ni][0], bhb[ni][1], bhb[ni][2], bhb[ni][3], rb);
                LDSM_X4(blb[ni][0], blb[ni][1], blb[ni][2], blb[ni][3], rb + BHL);
            }
#pragma unroll
            for (int mi = 0; mi < 2; mi++)
#pragma unroll
                for (int nj = 0; nj < NJ; nj++)
                    MMA_BF16(acc[mi][nj], ahb[mi], bhb[nj >> 1][nj & 1], bhb[nj >> 1][(nj & 1) + 2]);
#pragma unroll
            for (int mi = 0; mi < 2; mi++)
#pragma unroll
                for (int nj = 0; nj < NJ; nj++)
                    MMA_BF16(acc[mi][nj], ahb[mi], blb[nj >> 1][nj & 1], blb[nj >> 1][(nj & 1) + 2]);
#pragma unroll
            for (int mi = 0; mi < 2; mi++)
#pragma unroll
                for (int nj = 0; nj < NJ; nj++)
                    MMA_BF16(acc[mi][nj], alb[mi], bhb[nj >> 1][nj & 1], bhb[nj >> 1][(nj & 1) + 2]);
        }
    }

    const int gr = lane >> 2, gc = lane & 3;
    const bool second = DUAL && (m0 >= Dm);
#pragma unroll
    for (int mi = 0; mi < 2; mi++) {
#pragma unroll
        for (int half = 0; half < 2; half++) {
            const int m = m0 + wm + mi * 16 + gr + half * 8;
            const int mrow = second ? (m - Dm) : m;
            float bm = 0.0f;
            if ((EPI == 1 || EPI == 2) && BIASROW) bm = bias[m];
#pragma unroll
            for (int nj = 0; nj < NJ; nj++) {
                const int n = n0 + wn + nj * 8 + 2 * gc;
                float v0 = acc[mi][nj][half * 2 + 0];
                float v1 = acc[mi][nj][half * 2 + 1];
                if (EPI == 1 || EPI == 2) {
                    if (BIASROW) { v0 += bm; v1 += bm; }
                    else         { v0 += bias[n]; v1 += bias[n + 1]; }
                }
                if (EPI == 2 || (DUAL && second)) {
                    v0 *= sigmoidf_(v0); v1 *= sigmoidf_(v1);
                }
                if (EPI == 3) {
                    v0 = fmaxf(v0, 0.0f) + log1pf(expf(-fabsf(v0)));
                    v1 = fmaxf(v1, 0.0f) + log1pf(expf(-fabsf(v1)));
                }
                size_t idx = (size_t)mrow * Nn + n;
                if (DUAL && second) {
                    *(float2*)&Cf2[idx] = make_float2(v0, v1);
                } else {
                    if (WF32) *(float2*)&Cf[idx] = make_float2(v0, v1);
                    if (WSPLIT) {
                        bf16 h0 = __float2bfloat16(v0);
                        bf16 h1 = __float2bfloat16(v1);
                        __nv_bfloat162 hh; hh.x = h0; hh.y = h1;
                        __nv_bfloat162 ll;
                        ll.x = __float2bfloat16(v0 - __bfloat162float(h0));
                        ll.y = __float2bfloat16(v1 - __bfloat162float(h1));
                        *(__nv_bfloat162*)&Chi[idx] = hh;
                        *(__nv_bfloat162*)&Clo[idx] = ll;
                    }
                }
            }
        }
    }
}

// ---------------- int8 two-level quantization (per-row scale) ----------------
__global__ void __launch_bounds__(256) quant_rows(const float* __restrict__ A,
                                                  const float* __restrict__ B,
                                                  int8_t* __restrict__ Aq1,
                                                  int8_t* __restrict__ Aq2,
                                                  int8_t* __restrict__ Bq1,
                                                  int8_t* __restrict__ Bq2,
                                                  float* __restrict__ sA,
                                                  float* __restrict__ sB) {
    const int row = blockIdx.x;
    const bool isB = row >= Dm;
    const int r = isB ? row - Dm : row;
    const float* in = (isB ? B : A) + (size_t)r * Dm;
    int8_t* q1 = (isB ? Bq1 : Aq1) + (size_t)r * Dm;
    int8_t* q2 = (isB ? Bq2 : Aq2) + (size_t)r * Dm;
    const int tid = threadIdx.x;

    float4 v = *(const float4*)(in + tid * 4);
    float m = fmaxf(fmaxf(fabsf(v.x), fabsf(v.y)), fmaxf(fabsf(v.z), fabsf(v.w)));
    __shared__ float red[8];
#pragma unroll
    for (int off = 16; off; off >>= 1)
        m = fmaxf(m, __shfl_xor_sync(0xffffffffu, m, off));
    if ((tid & 31) == 0) red[tid >> 5] = m;
    __syncthreads();
    if (tid < 32) {
        float t2 = (tid < 8) ? red[tid] : 0.0f;
#pragma unroll
        for (int off = 4; off; off >>= 1)
            t2 = fmaxf(t2, __shfl_xor_sync(0xffffffffu, t2, off));
        if (tid == 0) {
            red[0] = fmaxf(t2, 1e-20f);
            if (isB) sB[r] = red[0] / 127.0f; else sA[r] = red[0] / 127.0f;
        }
    }
    __syncthreads();
    const float s = red[0] / 127.0f;
    const float inv = 127.0f / red[0];
    float vv[4] = {v.x, v.y, v.z, v.w};
    char c1[4], c2[4];
#pragma unroll
    for (int j = 0; j < 4; j++) {
        float qq1 = rintf(vv[j] * inv);
        float rres = vv[j] - s * qq1;
        float qq2 = fminf(fmaxf(rintf(rres * inv * 256.0f), -127.0f), 127.0f);
        c1[j] = (char)(int)qq1;
        c2[j] = (char)(int)qq2;
    }
    *(int*)(q1 + tid * 4) = *(int*)c1;
    *(int*)(q2 + tid * 4) = *(int*)c2;
}

// ---------------- int8 3-term IMMA GEMM (pilot: t = y @ xg^T) ----------------
__global__ void __launch_bounds__(256, 1)
gemm_i8(const int8_t* __restrict__ Aq1, const int8_t* __restrict__ Aq2,
        const int8_t* __restrict__ Bq1, const int8_t* __restrict__ Bq2,
        const float* __restrict__ sA, const float* __restrict__ sB,
        bf16* __restrict__ Chi, bf16* __restrict__ Clo, int Nn, int K)
{
    constexpr int TM = 128, TN = 64, NT = 256;
    constexpr int OFF_A2 = TM * 128;
    constexpr int OFF_B1 = TM * 256;
    constexpr int BL = TN * 128;
    constexpr int STAGEB = (TM + TN) * 256;  // 48KB
    constexpr int NBUF = 4, DEPTH = 3;
    constexpr int NJ = 4, NG = 2;            // warp tile 32x32

    extern __shared__ __align__(1024) char dyns[];
    const int tid = threadIdx.x;
    const int lane = tid & 31, warp = tid >> 5;
    const int m0 = blockIdx.y * TM, n0 = blockIdx.x * TN;
    const uint32_t dbase = smem_u32(dyns);
    const int S = K >> 7;   // 128 int8 per stage

    int acc0[2][NJ][4], acc1[2][NJ][4];
#pragma unroll
    for (int a = 0; a < 2; a++)
#pragma unroll
        for (int b = 0; b < NJ; b++)
#pragma unroll
            for (int c = 0; c < 4; c++) { acc0[a][b][c] = 0; acc1[a][b][c] = 0; }

    auto load_stage = [&](int s) {
        const uint32_t sb = dbase + (s % NBUF) * STAGEB;
        const int k0 = s << 7;
#pragma unroll
        for (int i = 0; i < 4; i++) {          // A: 128 rows x 128B, 16B chunks
            int q = tid + i * NT;
            int r = q >> 3, c = q & 7;
            uint32_t so = SWZ((uint32_t)(r * 128 + c * 16));
            size_t ga = (size_t)(m0 + r) * K + k0 + c * 16;
            cpa16(sb + so, Aq1 + ga);
            cpa16(sb + OFF_A2 + so, Aq2 + ga);
        }
#pragma unroll
        for (int i = 0; i < 2; i++) {          // B: 64 rows x 128B
            int q = tid + i * NT;
            int r = q >> 3, c = q & 7;
            uint32_t so = SWZ((uint32_t)(r * 128 + c * 16));
            size_t gb = (size_t)(n0 + r) * K + k0 + c * 16;
            cpa16(sb + OFF_B1 + so, Bq1 + gb);
            cpa16(sb + OFF_B1 + BL + so, Bq2 + gb);
        }
        asm volatile("cp.async.commit_group;" ::: "memory");
    };

#pragma unroll
    for (int s = 0; s < DEPTH; s++) load_stage(s);

    const int wm = (warp & 3) * 32, wn = (warp >> 2) * 32;
    const uint32_t frow = (lane & 7) + ((lane >> 3) & 1) * 8;
    const uint32_t fxor = (frow & 7) << 4;
    const uint32_t fcol = (lane >> 4) << 4;

    for (int s = 0; s < S; s++) {
        asm volatile("cp.async.wait_group %0;" :: "n"(DEPTH - 1) : "memory");
        __syncthreads();
        if (s + DEPTH < S) load_stage(s + DEPTH);
        else asm volatile("cp.async.commit_group;" ::: "memory");

        const uint32_t sb = dbase + (s % NBUF) * STAGEB;
#pragma unroll
        for (int ks = 0; ks < 4; ks++) {       // 4 x k32 per stage
            const uint32_t kc = (uint32_t)(ks * 32 + fcol) ^ fxor;
            uint32_t a1[2][4], a2[2][4], b1[NG][4], b2[NG][4];
#pragma unroll
            for (int mi = 0; mi < 2; mi++) {
                uint32_t ra = sb + (wm + mi * 16 + frow) * 128 + kc;
                LDSM_X4(a1[mi][0], a1[mi][1], a1[mi][2], a1[mi][3], ra);
                LDSM_X4(a2[mi][0], a2[mi][1], a2[mi][2], a2[mi][3], ra + OFF_A2);
            }
#pragma unroll
            for (int ni = 0; ni < NG; ni++) {
                uint32_t rb = sb + OFF_B1 + (wn + ni * 16 + frow) * 128 + kc;
                LDSM_X4(b1[ni][0], b1[ni][1], b1[ni][2], b1[ni][3], rb);
                LDSM_X4(b2[ni][0], b2[ni][1], b2[ni][2], b2[ni][3], rb + BL);
            }
#pragma unroll
            for (int mi = 0; mi < 2; mi++)
#pragma unroll
                for (int nj = 0; nj < NJ; nj++)
                    MMA_S8(acc0[mi][nj], a1[mi], b1[nj >> 1][nj & 1], b1[nj >> 1][(nj & 1) + 2]);
#pragma unroll
            for (int mi = 0; mi < 2; mi++)
#pragma unroll
                for (int nj = 0; nj < NJ; nj++)
                    MMA_S8(acc1[mi][nj], a1[mi], b2[nj >> 1][nj & 1], b2[nj >> 1][(nj & 1) + 2]);
#pragma unroll
            for (int mi = 0; mi < 2; mi++)
#pragma unroll
                for (int nj = 0; nj < NJ; nj++)
                    MMA_S8(acc1[mi][nj], a2[mi], b1[nj >> 1][nj & 1], b1[nj >> 1][(nj & 1) + 2]);
        }
    }

    const int gr = lane >> 2, gc = lane & 3;
#pragma unroll
    for (int mi = 0; mi < 2; mi++) {
#pragma unroll
        for (int half = 0; half < 2; half++) {
            const int m = m0 + wm + mi * 16 + gr + half * 8;
            const float sa = sA[m];
#pragma unroll
            for (int nj = 0; nj < NJ; nj++) {
                const int n = n0 + wn + nj * 8 + 2 * gc;
                float sb0 = sB[n], sb1 = sB[n + 1];
                float v0 = sa * sb0 * ((float)acc0[mi][nj][half * 2 + 0] +
                                       (float)acc1[mi][nj][half * 2 + 0] * (1.0f / 256.0f));
                float v1 = sa * sb1 * ((float)acc0[mi][nj][half * 2 + 1] +
                                       (float)acc1[mi][nj][half * 2 + 1] * (1.0f / 256.0f));
                size_t idx = (size_t)m * Nn + n;
                bf16 h0 = __float2bfloat16(v0);
                bf16 h1 = __float2bfloat16(v1);
                __nv_bfloat162 hh; hh.x = h0; hh.y = h1;
                __nv_bfloat162 ll;
                ll.x = __float2bfloat16(v0 - __bfloat162float(h0));
                ll.y = __float2bfloat16(v1 - __bfloat162float(h1));
                *(__nv_bfloat162*)&Chi[idx] = hh;
                *(__nv_bfloat162*)&Clo[idx] = ll;
            }
        }
    }
}

// ---------------- B/C projections -------------------------------------------
__global__ void __launch_bounds__(256) bc_kernel(const float* __restrict__ Xc,
                                                 const float* __restrict__ WB,
                                                 const float* __restrict__ WC,
                                                 float* __restrict__ Bo,
                                                 float* __restrict__ Co) {
    __shared__ float row[Dm];
    const int l = blockIdx.x;
    for (int k = threadIdx.x; k < Dm; k += 256) row[k] = Xc[(size_t)l * Dm + k];
    __syncthreads();
    const int part = threadIdx.x & 7;
    const int out = threadIdx.x >> 3;
    const int n = out & 15;
    const float* W = (out < 16) ? WB : WC;
    float s = 0.0f;
    for (int k = part; k < Dm; k += 8) s = fmaf(row[k], W[k * Ns + n], s);
#pragma unroll
    for (int off = 4; off; off >>= 1) s += __shfl_down_sync(0xffffffffu, s, off, 8);
    if (part == 0) {
        if (out < 16) Bo[l * Ns + n] = s;
        else          Co[l * Ns + n] = s;
    }
}

// ---------------- selective scan v5 (fp32 y output) --------------------------
constexpr int SCH = 64;
constexpr int SNC = Dm / SCH;

__global__ void __launch_bounds__(128) scan_kernel(const float* __restrict__ delta,
                                                   const float* __restrict__ Xc,
                                                   const float* __restrict__ Bm,
                                                   const float* __restrict__ Cm,
                                                   const float* __restrict__ Alog,
                                                   float* __restrict__ Y) {
    __shared__ float sD[2][SCH][8];
    __shared__ float sX[2][SCH][8];
    __shared__ float sB[2][SCH][16];
    __shared__ float sC[2][SCH][16];

    const int tid = threadIdx.x;
    const int n = tid & 15;
    const int dl = tid >> 4;
    const int d0 = blockIdx.x * 8;
    const int d = d0 + dl;
    const float a = -expf(Alog[d * Ns + n]);

    auto load_chunk = [&](int c) {
        const int buf = c & 1;
        const int l0 = c * SCH;
        {
            int j = tid >> 1, hq = tid & 1;
            const size_t src = (size_t)(l0 + j) * Dm + d0 + hq * 4;
            cpa16(smem_u32(&sD[buf][j][hq * 4]), delta + src);
            cpa16(smem_u32(&sX[buf][j][hq * 4]), Xc + src);
        }
#pragma unroll
        for (int i = 0; i < 2; i++) {
            int task = tid + i * 128;
            int j = task >> 2, q = task & 3;
            cpa16(smem_u32(&sB[buf][j][q * 4]), Bm + (size_t)(l0 + j) * Ns + q * 4);
            cpa16(smem_u32(&sC[buf][j][q * 4]), Cm + (size_t)(l0 + j) * Ns + q * 4);
        }
        asm volatile("cp.async.commit_group;" ::: "memory");
    };

    load_chunk(0);
    float h = 0.0f;

    for (int c = 0; c < SNC; c++) {
        const int buf = c & 1;
        if (c + 1 < SNC) {
            load_chunk(c + 1);
            asm volatile("cp.async.wait_group 1;" ::: "memory");
        } else {
            asm volatile("cp.async.wait_group 0;" ::: "memory");
        }
        __syncthreads();

#pragma unroll 4
        for (int j = 0; j < SCH; j++) {
            float de = sD[buf][j][dl];
            float xv = sX[buf][j][dl];
            float bv = sB[buf][j][n];
            float cv = sC[buf][j][n];
            float e = __expf(de * a);
            h = fmaf(e, h, de * xv * bv);
            float pr = h * cv;
#pragma unroll
            for (int off = 8; off; off >>= 1)
                pr += __shfl_down_sync(0xffffffffu, pr, off, 16);
            if (n == 0)
                Y[(size_t)(c * SCH + j) * Dm + d] = pr;
        }
        __syncthreads();
    }
}

// ---------------- launch ------------------------------------------------------
extern "C" void kernel_launch(void* const* d_in, const int* in_sizes, int n_in,
                              void* d_out, int out_size) {
    const float* x    = (const float*)d_in[0];
    const float* Wp   = (const float*)d_in[1];
    const float* bp   = (const float*)d_in[2];
    const float* cw   = (const float*)d_in[3];
    const float* cb   = (const float*)d_in[4];
    const float* Alog = (const float*)d_in[5];
    const float* Wd   = (const float*)d_in[6];
    const float* WB   = (const float*)d_in[7];
    const float* WC   = (const float*)d_in[8];
    float* out = (float*)d_out;

    bf16 *xhi, *xlo, *Wphi, *Wplo, *cwhi, *cwlo, *WdThi, *WdTlo;
    bf16 *cBhi, *cBlo, *xchi, *xclo, *thi, *tlo;
    float *p0, *xgf, *xc, *del, *Bm, *Cm, *yf, *scy, *scxg;
    int8_t *yq1, *yq2, *xgq1, *xgq2;
    cudaGetSymbolAddress((void**)&xhi, g_xhi);   cudaGetSymbolAddress((void**)&xlo, g_xlo);
    cudaGetSymbolAddress((void**)&Wphi, g_Wphi); cudaGetSymbolAddress((void**)&Wplo, g_Wplo);
    cudaGetSymbolAddress((void**)&cwhi, g_cwhi); cudaGetSymbolAddress((void**)&cwlo, g_cwlo);
    cudaGetSymbolAddress((void**)&WdThi, g_WdThi); cudaGetSymbolAddress((void**)&WdTlo, g_WdTlo);
    cudaGetSymbolAddress((void**)&cBhi, g_cBhi); cudaGetSymbolAddress((void**)&cBlo, g_cBlo);
    cudaGetSymbolAddress((void**)&xchi, g_xchi); cudaGetSymbolAddress((void**)&xclo, g_xclo);
    cudaGetSymbolAddress((void**)&thi, g_thi);   cudaGetSymbolAddress((void**)&tlo, g_tlo);
    cudaGetSymbolAddress((void**)&p0, g_p0);
    cudaGetSymbolAddress((void**)&xgf, g_xgf);
    cudaGetSymbolAddress((void**)&xc, g_xc);
    cudaGetSymbolAddress((void**)&del, g_delta);
    cudaGetSymbolAddress((void**)&Bm, g_Bm);
    cudaGetSymbolAddress((void**)&Cm, g_Cm);
    cudaGetSymbolAddress((void**)&yf, g_yf);
    cudaGetSymbolAddress((void**)&yq1, g_yq1);   cudaGetSymbolAddress((void**)&yq2, g_yq2);
    cudaGetSymbolAddress((void**)&xgq1, g_xgq1); cudaGetSymbolAddress((void**)&xgq2, g_xgq2);
    cudaGetSymbolAddress((void**)&scy, g_scy);   cudaGetSymbolAddress((void**)&scxg, g_scxg);

    const int SMEM128 = 3 * 65536;
    const int SMEM64  = 4 * 49152;
    cudaFuncSetAttribute(gemm_mma<512, 128, 128, 1, false, true,  false, true>,  cudaFuncAttributeMaxDynamicSharedMemorySize, SMEM128);
    cudaFuncSetAttribute(gemm_mma<256, 128, 64,  2, true,  true,  true,  false>, cudaFuncAttributeMaxDynamicSharedMemorySize, SMEM64);
    cudaFuncSetAttribute(gemm_mma<256, 128, 64,  3, false, true,  false, false>, cudaFuncAttributeMaxDynamicSharedMemorySize, SMEM64);
    cudaFuncSetAttribute(gemm_mma<256, 128, 64,  1, false, true,  false, false>, cudaFuncAttributeMaxDynamicSharedMemorySize, SMEM64);
    cudaFuncSetAttribute(gemm_i8, cudaFuncAttributeMaxDynamicSharedMemorySize, SMEM64);

    // #1: all independent prep
    prep_fused<<<4096, 256>>>(x, xhi, xlo, Wp, Wphi, Wplo, Wd, WdThi, WdTlo,
                              cw, cwhi, cwlo);

    // #2: fused input projections: p0 fp32 + xg fp32 (silu)
    gemm_mma<512, 128, 128, 1, false, true, false, true><<<dim3(8, 16), 512, SMEM128>>>(
        xhi, xlo, Wphi, Wplo, bp, p0, nullptr, nullptr, xgf, Dm, Dm);

    // #3: conv B operand build
    conv_b_build<<<dim3(32, 32), 256>>>(p0, cBhi, cBlo);

    // #4: conv as GEMM (K = 3072)
    gemm_mma<256, 128, 64, 2, true, true, true, false><<<dim3(16, 8), 256, SMEM64>>>(
        cwhi, cwlo, cBhi, cBlo, cb, xc, xchi, xclo, nullptr, Dm, KC);

    // #5: delta = softplus(xc @ W_delta)
    gemm_mma<256, 128, 64, 3, false, true, false, false><<<dim3(16, 8), 256, SMEM64>>>(
        xchi, xclo, WdThi, WdTlo, nullptr, del, nullptr, nullptr, nullptr, Dm, Dm);

    // #6-7: B/C projections + scan (fp32 y)
    bc_kernel<<<Dm, 256>>>(xc, WB, WC, Bm, Cm);
    scan_kernel<<<Dm / 8, 128>>>(del, xc, Bm, Cm, Alog, yf);

    // #8: quantize y (rows 0..1023) and xg (rows 1024..2047)
    quant_rows<<<2 * Dm, 256>>>(yf, xgf, yq1, yq2, xgq1, xgq2, scy, scxg);

    // #9: t = y @ xg^T  (int8 pilot)
    gemm_i8<<<dim3(16, 8), 256, SMEM64>>>(yq1, yq2, xgq1, xgq2, scy, scxg,
                                          thi, tlo, Dm, Dm);

    // #10: out = t @ Wp^T + b
    gemm_mma<256, 128, 64, 1, false, true, false, false><<<dim3(16, 8), 256, SMEM64>>>(
        thi, tlo, Wphi, Wplo, bp, out, nullptr, nullptr, nullptr, Dm, Dm);
}